// round 16
// baseline (speedup 1.0000x reference)
#include <cuda_runtime.h>

#define B_SZ    16384
#define NL      131072
#define THREADS 256
#define NBLOCKS 512                    // 512*256 = 131072 threads = NL
#define NTHREADS (NBLOCKS * THREADS)   // 131072
#define NCLS    20
// cells: 6 per thread + 1 extra for tid < 16384  (6*131072 + 16384 = 802816)

__device__ double       g_acc   = 0.0;
__device__ unsigned int g_count = 0;

__device__ __forceinline__ float iou_pair(float ax, float ay, float aw, float ah,
                                          float gx, float gy, float gw, float gh) {
    float ax1 = ax - aw * 0.5f, ax2 = ax + aw * 0.5f;
    float ay1 = ay - ah * 0.5f, ay2 = ay + ah * 0.5f;
    float gx1 = gx - gw * 0.5f, gx2 = gx + gw * 0.5f;
    float gy1 = gy - gh * 0.5f, gy2 = gy + gh * 0.5f;
    float iw = fmaxf(0.0f, fminf(ax2, gx2) - fmaxf(ax1, gx1));
    float ih = fmaxf(0.0f, fminf(ay2, gy2) - fmaxf(ay1, gy1));
    float inter = iw * ih;
    float uni = aw * ah + gw * gh - inter;
    return inter / (uni + 1e-6f);
}

__global__ void __launch_bounds__(THREADS)
yolo_loss_kernel(const float* __restrict__ out, const float* __restrict__ labels,
                 float* __restrict__ result) {
    unsigned tid = blockIdx.x * THREADS + threadIdx.x;   // < 131072

    // ---------- label header loads ----------
    const float2* Lp = reinterpret_cast<const float2*>(labels + (size_t)tid * 6);
    float2 l0 = __ldg(Lp + 0);   // b, cls
    float2 l1 = __ldg(Lp + 1);   // gx, gy
    float2 l2 = __ldg(Lp + 2);   // gw, gh

    // ---------- cell (no-object) loads: 6(+1) strided float2 ----------
    float2 cv[6];
    #pragma unroll
    for (int k = 0; k < 6; k++) {
        unsigned cell = tid + k * NTHREADS;
        cv[k] = *reinterpret_cast<const float2*>(out + (size_t)cell * 30 + 20);
    }
    bool extra = tid < 16384u;
    float2 ce = make_float2(0.0f, 0.0f);
    if (extra) {
        unsigned cell = 6u * NTHREADS + tid;
        ce = *reinterpret_cast<const float2*>(out + (size_t)cell * 30 + 20);
    }

    // ---------- label cell gather (depends on header) ----------
    int b = (int)l0.x;
    int c = (int)l0.y;
    float gx = l1.x, gy = l1.y, gw = l2.x, gh = l2.y;

    float rowf = floorf(gx * 7.0f);
    float colf = floorf(gy * 7.0f);
    int row = (int)rowf, col = (int)colf;

    const float2* p2 = reinterpret_cast<const float2*>(
        out + ((size_t)b * 49 + (size_t)(row * 7 + col)) * 30);

    // Batch A: channels 0..15
    float2 va[8];
    #pragma unroll
    for (int k = 0; k < 8; k++) va[k] = __ldg(p2 + k);

    // ---- consume cell loads while gather is in flight ----
    float noobj = 0.0f;
    #pragma unroll
    for (int k = 0; k < 6; k++)
        noobj += cv[k].x * cv[k].x + cv[k].y * cv[k].y;
    if (extra) noobj += ce.x * ce.x + ce.y * ce.y;
    noobj *= 0.5f;

    // class loss pieces from batch A
    float sumsq = 0.0f;
    float pvc = 0.0f;
    #pragma unroll
    for (int k = 0; k < 8; k++) {
        sumsq += va[k].x * va[k].x + va[k].y * va[k].y;
        if (c == 2 * k)     pvc = va[k].x;
        if (c == 2 * k + 1) pvc = va[k].y;
    }

    // Batch B: channels 16..29
    float2 vb[7];
    #pragma unroll
    for (int k = 0; k < 7; k++) vb[k] = __ldg(p2 + 8 + k);

    sumsq += vb[0].x * vb[0].x + vb[0].y * vb[0].y
           + vb[1].x * vb[1].x + vb[1].y * vb[1].y;
    if (c == 16) pvc = vb[0].x;
    if (c == 17) pvc = vb[0].y;
    if (c == 18) pvc = vb[1].x;
    if (c == 19) pvc = vb[1].y;
    float cls = sumsq - 2.0f * pvc + 1.0f;

    // channels: 20=vb[2].x 21=vb[2].y 22=vb[3].x 23=vb[3].y 24=vb[4].x
    //           25=vb[4].y 26=vb[5].x 27=vb[5].y 28=vb[6].x 29=vb[6].y
    const float inv_s = 1.0f / 7.0f;
    float iou1 = iou_pair((rowf + vb[3].x) * inv_s, (colf + vb[3].y) * inv_s,
                          vb[4].x, vb[4].y, gx, gy, gw, gh);
    float iou2 = iou_pair((rowf + vb[5].x) * inv_s, (colf + vb[5].y) * inv_s,
                          vb[6].x, vb[6].y, gx, gy, gw, gh);
    bool use1 = (iou1 >= iou2);

    float gcx = gx * 7.0f - rowf;
    float gcy = gy * 7.0f - colf;

    float px = use1 ? vb[3].x : vb[5].x;
    float py = use1 ? vb[3].y : vb[5].y;
    float pw = use1 ? vb[4].x : vb[6].x;
    float ph = use1 ? vb[4].y : vb[6].y;

    const float eps = 1e-6f;
    float dx = px - gcx;
    float dy = py - gcy;
    float dw = sqrtf(pw + eps) - sqrtf(gw + eps);
    float dh = sqrtf(ph + eps) - sqrtf(gh + eps);
    float coor = 5.0f * (dx * dx + dy * dy + dw * dw + dh * dh);

    float cp = use1 ? vb[2].x : vb[2].y;
    float ct = use1 ? iou1 : iou2;
    float cd = cp - ct;
    float conf = cd * cd - 0.5f * cp * cp;

    float local = noobj + cls + coor + conf;

    // block reduction: warp shuffles + shared
    #pragma unroll
    for (int o = 16; o > 0; o >>= 1)
        local += __shfl_down_sync(0xffffffffu, local, o);

    __shared__ float wsum[THREADS / 32];
    int lane = threadIdx.x & 31;
    int wid = threadIdx.x >> 5;
    if (lane == 0) wsum[wid] = local;
    __syncthreads();

    if (wid == 0) {
        float v = (lane < THREADS / 32) ? wsum[lane] : 0.0f;
        #pragma unroll
        for (int o = 4; o > 0; o >>= 1)
            v += __shfl_down_sync(0xffffffffu, v, o);
        if (lane == 0) {
            atomicAdd(&g_acc, (double)v);
            __threadfence();
            unsigned t = atomicAdd(&g_count, 1u);
            if (t == (unsigned)(gridDim.x - 1)) {
                // last block: publish result and reset state for next replay
                result[0] = (float)(g_acc / (double)B_SZ);
                g_acc = 0.0;
                g_count = 0u;
            }
        }
    }
}

extern "C" void kernel_launch(void* const* d_in, const int* in_sizes, int n_in,
                              void* d_out, int out_size) {
    const float* output = (const float*)d_in[0];
    const float* labels = (const float*)d_in[1];
    float* out = (float*)d_out;

    yolo_loss_kernel<<<NBLOCKS, THREADS>>>(output, labels, out);
}

// round 17
// speedup vs baseline: 1.0173x; 1.0173x over previous
#include <cuda_runtime.h>

#define B_SZ    16384
#define NL      131072
#define THREADS 256
#define NBLOCKS 512                    // 512*256 = 131072 threads = NL
#define NTHREADS (NBLOCKS * THREADS)   // 131072
#define NCLS    20
// cells: 6 per thread + 1 extra for tid < 16384  (6*131072 + 16384 = 802816)

__device__ double       g_acc   = 0.0;
__device__ unsigned int g_count = 0;

__device__ __forceinline__ float iou_pair(float ax, float ay, float aw, float ah,
                                          float gx, float gy, float gw, float gh) {
    float ax1 = ax - aw * 0.5f, ax2 = ax + aw * 0.5f;
    float ay1 = ay - ah * 0.5f, ay2 = ay + ah * 0.5f;
    float gx1 = gx - gw * 0.5f, gx2 = gx + gw * 0.5f;
    float gy1 = gy - gh * 0.5f, gy2 = gy + gh * 0.5f;
    float iw = fmaxf(0.0f, fminf(ax2, gx2) - fmaxf(ax1, gx1));
    float ih = fmaxf(0.0f, fminf(ay2, gy2) - fmaxf(ay1, gy1));
    float inter = iw * ih;
    float uni = aw * ah + gw * gh - inter;
    return inter / (uni + 1e-6f);
}

__global__ void __launch_bounds__(THREADS)
yolo_loss_kernel(const float* __restrict__ out, const float* __restrict__ labels,
                 float* __restrict__ result) {
    unsigned tid = blockIdx.x * THREADS + threadIdx.x;   // < 131072

    // ---------- label header loads ----------
    const float2* Lp = reinterpret_cast<const float2*>(labels + (size_t)tid * 6);
    float2 l0 = __ldg(Lp + 0);   // b, cls
    float2 l1 = __ldg(Lp + 1);   // gx, gy
    float2 l2 = __ldg(Lp + 2);   // gw, gh

    // ---------- cell (no-object) loads: 6(+1) strided float2 ----------
    float2 cv[6];
    #pragma unroll
    for (int k = 0; k < 6; k++) {
        unsigned cell = tid + k * NTHREADS;
        cv[k] = *reinterpret_cast<const float2*>(out + (size_t)cell * 30 + 20);
    }
    bool extra = tid < 16384u;
    float2 ce = make_float2(0.0f, 0.0f);
    if (extra) {
        unsigned cell = 6u * NTHREADS + tid;
        ce = *reinterpret_cast<const float2*>(out + (size_t)cell * 30 + 20);
    }

    // ---------- label cell gather (depends on header) ----------
    int b = (int)l0.x;
    int c = (int)l0.y;
    float gx = l1.x, gy = l1.y, gw = l2.x, gh = l2.y;

    float rowf = floorf(gx * 7.0f);
    float colf = floorf(gy * 7.0f);
    int row = (int)rowf, col = (int)colf;

    const float2* p2 = reinterpret_cast<const float2*>(
        out + ((size_t)b * 49 + (size_t)(row * 7 + col)) * 30);

    // Batch A: channels 0..15
    float2 va[8];
    #pragma unroll
    for (int k = 0; k < 8; k++) va[k] = __ldg(p2 + k);

    // ---- consume cell loads while gather is in flight ----
    float noobj = 0.0f;
    #pragma unroll
    for (int k = 0; k < 6; k++)
        noobj += cv[k].x * cv[k].x + cv[k].y * cv[k].y;
    if (extra) noobj += ce.x * ce.x + ce.y * ce.y;
    noobj *= 0.5f;

    // class loss pieces from batch A
    float sumsq = 0.0f;
    float pvc = 0.0f;
    #pragma unroll
    for (int k = 0; k < 8; k++) {
        sumsq += va[k].x * va[k].x + va[k].y * va[k].y;
        if (c == 2 * k)     pvc = va[k].x;
        if (c == 2 * k + 1) pvc = va[k].y;
    }

    // Batch B: channels 16..29
    float2 vb[7];
    #pragma unroll
    for (int k = 0; k < 7; k++) vb[k] = __ldg(p2 + 8 + k);

    sumsq += vb[0].x * vb[0].x + vb[0].y * vb[0].y
           + vb[1].x * vb[1].x + vb[1].y * vb[1].y;
    if (c == 16) pvc = vb[0].x;
    if (c == 17) pvc = vb[0].y;
    if (c == 18) pvc = vb[1].x;
    if (c == 19) pvc = vb[1].y;
    float cls = sumsq - 2.0f * pvc + 1.0f;

    // channels: 20=vb[2].x 21=vb[2].y 22=vb[3].x 23=vb[3].y 24=vb[4].x
    //           25=vb[4].y 26=vb[5].x 27=vb[5].y 28=vb[6].x 29=vb[6].y
    const float inv_s = 1.0f / 7.0f;
    float iou1 = iou_pair((rowf + vb[3].x) * inv_s, (colf + vb[3].y) * inv_s,
                          vb[4].x, vb[4].y, gx, gy, gw, gh);
    float iou2 = iou_pair((rowf + vb[5].x) * inv_s, (colf + vb[5].y) * inv_s,
                          vb[6].x, vb[6].y, gx, gy, gw, gh);
    bool use1 = (iou1 >= iou2);

    float gcx = gx * 7.0f - rowf;
    float gcy = gy * 7.0f - colf;

    float px = use1 ? vb[3].x : vb[5].x;
    float py = use1 ? vb[3].y : vb[5].y;
    float pw = use1 ? vb[4].x : vb[6].x;
    float ph = use1 ? vb[4].y : vb[6].y;

    const float eps = 1e-6f;
    float dx = px - gcx;
    float dy = py - gcy;
    float dw = sqrtf(pw + eps) - sqrtf(gw + eps);
    float dh = sqrtf(ph + eps) - sqrtf(gh + eps);
    float coor = 5.0f * (dx * dx + dy * dy + dw * dw + dh * dh);

    float cp = use1 ? vb[2].x : vb[2].y;
    float ct = use1 ? iou1 : iou2;
    float cd = cp - ct;
    float conf = cd * cd - 0.5f * cp * cp;

    float local = noobj + cls + coor + conf;

    // block reduction: warp shuffles + shared
    #pragma unroll
    for (int o = 16; o > 0; o >>= 1)
        local += __shfl_down_sync(0xffffffffu, local, o);

    __shared__ float wsum[THREADS / 32];
    int lane = threadIdx.x & 31;
    int wid = threadIdx.x >> 5;
    if (lane == 0) wsum[wid] = local;
    __syncthreads();

    if (wid == 0) {
        float v = (lane < THREADS / 32) ? wsum[lane] : 0.0f;
        #pragma unroll
        for (int o = 4; o > 0; o >>= 1)
            v += __shfl_down_sync(0xffffffffu, v, o);
        if (lane == 0) {
            atomicAdd(&g_acc, (double)v);
            __threadfence();
            unsigned t = atomicAdd(&g_count, 1u);
            if (t == (unsigned)(gridDim.x - 1)) {
                // last block: publish result and reset state for next replay
                result[0] = (float)(g_acc / (double)B_SZ);
                g_acc = 0.0;
                g_count = 0u;
            }
        }
    }
}

extern "C" void kernel_launch(void* const* d_in, const int* in_sizes, int n_in,
                              void* d_out, int out_size) {
    const float* output = (const float*)d_in[0];
    const float* labels = (const float*)d_in[1];
    float* out = (float*)d_out;

    yolo_loss_kernel<<<NBLOCKS, THREADS>>>(output, labels, out);
}